// round 1
// baseline (speedup 1.0000x reference)
#include <cuda_runtime.h>
#include <cstdint>

// Problem dims
#define B_  256
#define T_  64
#define K_  49
#define H_  512
#define A_  49          // projection dim (== K)
#define BT  (B_ * T_)       // 16384
#define BK  (B_ * K_)       // 12544
#define BTH ((size_t)BT * H_)   // 8388608
#define BTK ((size_t)BT * K_)   // 802816

// Scratch (device globals; no allocations allowed)
__device__ float g_cv[B_ * K_ * A_];    // content_v  [b,k,a]
__device__ float g_cg[B_ * T_ * A_];    // content_g  [b,t,a]
__device__ float g_zext[B_ * T_];       // z_ext      [b,t]

__device__ __forceinline__ float tanh_approx(float x) {
    float y;
    asm("tanh.approx.f32 %0, %1;" : "=f"(y) : "f"(x));
    return y;
}

// ---------------------------------------------------------------------------
// Row-GEMM: out[m][a] = sum_h X[m][h] * W[a][h],  X:(M,512) W:(49,512)
// TILE_M=64 rows/block, 128 threads: 16 m-threads x 8 a-threads (q==7 idle
// in compute). Each thread: 4 rows x 7 a accumulators, float4 smem reads.
// ---------------------------------------------------------------------------
#define TILE_M 64
#define HC     64
#define XPITCH 68
#define WPITCH 68

struct AccBlk { float a[4][7]; };

__device__ __forceinline__ void rowgemm_core(
    const float* __restrict__ X, const float* __restrict__ W,
    int row0, int tid, float* Xs, float* Ws, AccBlk& acc)
{
    const int q   = tid & 7;
    const int mth = tid >> 3;
    #pragma unroll
    for (int i = 0; i < 4; i++)
        #pragma unroll
        for (int j = 0; j < 7; j++) acc.a[i][j] = 0.f;

    for (int hc = 0; hc < H_; hc += HC) {
        __syncthreads();
        // load X tile: 64 rows x 16 float4
        for (int idx = tid; idx < TILE_M * (HC/4); idx += 128) {
            int r = idx >> 4, c = idx & 15;
            float4 v = *(const float4*)&X[(size_t)(row0 + r) * H_ + hc + c*4];
            *(float4*)&Xs[r * XPITCH + c*4] = v;
        }
        // load W tile: 49 rows x 16 float4
        for (int idx = tid; idx < A_ * (HC/4); idx += 128) {
            int r = idx >> 4, c = idx & 15;
            float4 v = *(const float4*)&W[(size_t)r * H_ + hc + c*4];
            *(float4*)&Ws[r * WPITCH + c*4] = v;
        }
        __syncthreads();
        if (q < 7) {
            #pragma unroll
            for (int h4 = 0; h4 < 16; h4++) {
                float4 w[7];
                #pragma unroll
                for (int j = 0; j < 7; j++)
                    w[j] = *(const float4*)&Ws[(q*7 + j) * WPITCH + h4*4];
                #pragma unroll
                for (int i = 0; i < 4; i++) {
                    float4 x = *(const float4*)&Xs[(mth*4 + i) * XPITCH + h4*4];
                    #pragma unroll
                    for (int j = 0; j < 7; j++) {
                        float s = acc.a[i][j];
                        s = fmaf(x.x, w[j].x, s);
                        s = fmaf(x.y, w[j].y, s);
                        s = fmaf(x.z, w[j].z, s);
                        s = fmaf(x.w, w[j].w, s);
                        acc.a[i][j] = s;
                    }
                }
            }
        }
    }
}

__global__ __launch_bounds__(128)
void rowgemm_cv_kernel(const float* __restrict__ X, const float* __restrict__ W)
{
    __shared__ float Xs[TILE_M * XPITCH];
    __shared__ float Ws[A_ * WPITCH];
    int tid = threadIdx.x, row0 = blockIdx.x * TILE_M;
    AccBlk acc;
    rowgemm_core(X, W, row0, tid, Xs, Ws, acc);
    int q = tid & 7, mth = tid >> 3;
    if (q < 7) {
        #pragma unroll
        for (int i = 0; i < 4; i++) {
            int m = row0 + mth*4 + i;
            #pragma unroll
            for (int j = 0; j < 7; j++)
                g_cv[(size_t)m * A_ + q*7 + j] = acc.a[i][j];
        }
    }
}

__global__ __launch_bounds__(128)
void rowgemm_cg_kernel(const float* __restrict__ X, const float* __restrict__ W)
{
    __shared__ float Xs[TILE_M * XPITCH];
    __shared__ float Ws[A_ * WPITCH];
    int tid = threadIdx.x, row0 = blockIdx.x * TILE_M;
    AccBlk acc;
    rowgemm_core(X, W, row0, tid, Xs, Ws, acc);
    int q = tid & 7, mth = tid >> 3;
    if (q < 7) {
        #pragma unroll
        for (int i = 0; i < 4; i++) {
            int m = row0 + mth*4 + i;
            #pragma unroll
            for (int j = 0; j < 7; j++)
                g_cg[(size_t)m * A_ + q*7 + j] = acc.a[i][j];
        }
    }
}

// cs = s_t @ Ws^T + cg ; z_ext = sum_a tanh(cs[a]) * Wh[a]
__global__ __launch_bounds__(128)
void cs_zext_kernel(const float* __restrict__ X, const float* __restrict__ W,
                    const float* __restrict__ Wh)
{
    __shared__ float Xs[TILE_M * XPITCH];
    __shared__ float Ws[A_ * WPITCH];
    __shared__ float red[TILE_M][8];
    int tid = threadIdx.x, row0 = blockIdx.x * TILE_M;
    AccBlk acc;
    rowgemm_core(X, W, row0, tid, Xs, Ws, acc);
    int q = tid & 7, mth = tid >> 3;
    if (q < 7) {
        #pragma unroll
        for (int i = 0; i < 4; i++) {
            int m = row0 + mth*4 + i;
            const float* cgrow = &g_cg[(size_t)m * A_];
            float p = 0.f;
            #pragma unroll
            for (int j = 0; j < 7; j++) {
                int a = q*7 + j;
                float cs = acc.a[i][j] + __ldg(&cgrow[a]);
                p = fmaf(tanh_approx(cs), __ldg(&Wh[a]), p);
            }
            red[mth*4 + i][q] = p;
        }
    }
    __syncthreads();
    if (tid < TILE_M) {
        float z = 0.f;
        #pragma unroll
        for (int qq = 0; qq < 7; qq++) z += red[tid][qq];
        g_zext[row0 + tid] = z;
    }
}

// ---------------------------------------------------------------------------
// z_t + softmax(alpha) + extended softmax(beta). One block per batch b.
// ---------------------------------------------------------------------------
__global__ __launch_bounds__(256)
void zsoft_kernel(const float* __restrict__ Wh,
                  float* __restrict__ out_alpha, float* __restrict__ out_beta)
{
    const int b = blockIdx.x;
    __shared__ float cvs[K_ * 50];
    __shared__ float cgs[T_ * 50];
    __shared__ float whs[A_];
    __shared__ float zes[T_];
    __shared__ float zs[T_ * 50];
    int tid = threadIdx.x;

    for (int i = tid; i < K_ * A_; i += 256)
        cvs[(i / A_) * 50 + (i % A_)] = g_cv[(size_t)b * K_ * A_ + i];
    for (int i = tid; i < T_ * A_; i += 256)
        cgs[(i / A_) * 50 + (i % A_)] = g_cg[(size_t)b * T_ * A_ + i];
    if (tid < A_) whs[tid] = Wh[tid];
    if (tid < T_) zes[tid] = g_zext[b * T_ + tid];
    __syncthreads();

    for (int item = tid; item < T_ * K_; item += 256) {
        int t = item / K_, k = item % K_;
        const float* cgrow = &cgs[t * 50];
        const float* cvrow = &cvs[k * 50];
        float s = 0.f;
        #pragma unroll
        for (int a = 0; a < A_; a++)
            s = fmaf(tanh_approx(cgrow[a] + cvrow[a]), whs[a], s);
        zs[t * 50 + k] = s;
    }
    __syncthreads();

    int warp = tid >> 5, lane = tid & 31;
    for (int t = warp; t < T_; t += 8) {
        float z1 = (lane < K_)      ? zs[t*50 + lane]      : -1e30f;
        float z2 = (lane + 32 < K_) ? zs[t*50 + lane + 32] : -1e30f;
        float m = fmaxf(z1, z2);
        #pragma unroll
        for (int o = 16; o; o >>= 1) m = fmaxf(m, __shfl_xor_sync(0xffffffffu, m, o));
        float e1 = (lane < K_)      ? __expf(z1 - m) : 0.f;
        float e2 = (lane + 32 < K_) ? __expf(z2 - m) : 0.f;
        float s = e1 + e2;
        #pragma unroll
        for (int o = 16; o; o >>= 1) s += __shfl_xor_sync(0xffffffffu, s, o);
        float inv = 1.f / s;
        size_t bt = (size_t)b * T_ + t;
        if (lane < K_)      out_alpha[bt * K_ + lane]      = e1 * inv;
        if (lane + 32 < K_) out_alpha[bt * K_ + lane + 32] = e2 * inv;
        if (lane == 0) {
            float ze = zes[t];
            float m2 = fmaxf(m, ze);
            float ee = __expf(ze - m2);
            float denom = s * __expf(m - m2) + ee;
            out_beta[bt] = ee / denom;
        }
    }
}

// ---------------------------------------------------------------------------
// c_hat = beta*s_t + (1-beta) * (alpha @ V).  Block: (b, 128-wide h chunk).
// 256 threads = 16 h-threads x 16 t-threads; thread: 4 t x 8 h.
// ---------------------------------------------------------------------------
__global__ __launch_bounds__(256)
void chat_kernel(const float* __restrict__ V, const float* __restrict__ s_t,
                 const float* __restrict__ alpha, const float* __restrict__ beta,
                 float* __restrict__ out)
{
    const int b  = blockIdx.y;
    const int hc = blockIdx.x * 128;
    __shared__ float Vs[K_ * 128];
    __shared__ float as[T_ * 51];
    __shared__ float bs[T_];
    int tid = threadIdx.x;

    for (int idx = tid; idx < K_ * 32; idx += 256) {     // 49 rows x 32 float4
        int k = idx >> 5, c = idx & 31;
        *(float4*)&Vs[k * 128 + c*4] =
            *(const float4*)&V[((size_t)b * K_ + k) * H_ + hc + c*4];
    }
    for (int i = tid; i < T_ * K_; i += 256)
        as[(i / K_) * 51 + (i % K_)] = alpha[(size_t)b * T_ * K_ + i];
    if (tid < T_) bs[tid] = beta[(size_t)b * T_ + tid];
    __syncthreads();

    const int hi = tid & 15, ti = tid >> 4;
    float4 acc0[4], acc1[4];
    #pragma unroll
    for (int j = 0; j < 4; j++) {
        acc0[j] = make_float4(0.f, 0.f, 0.f, 0.f);
        acc1[j] = make_float4(0.f, 0.f, 0.f, 0.f);
    }
    for (int k = 0; k < K_; k++) {
        float4 v0 = *(const float4*)&Vs[k * 128 + hi*8];
        float4 v1 = *(const float4*)&Vs[k * 128 + hi*8 + 4];
        #pragma unroll
        for (int j = 0; j < 4; j++) {
            float a = as[(ti + 16*j) * 51 + k];
            acc0[j].x = fmaf(a, v0.x, acc0[j].x);
            acc0[j].y = fmaf(a, v0.y, acc0[j].y);
            acc0[j].z = fmaf(a, v0.z, acc0[j].z);
            acc0[j].w = fmaf(a, v0.w, acc0[j].w);
            acc1[j].x = fmaf(a, v1.x, acc1[j].x);
            acc1[j].y = fmaf(a, v1.y, acc1[j].y);
            acc1[j].z = fmaf(a, v1.z, acc1[j].z);
            acc1[j].w = fmaf(a, v1.w, acc1[j].w);
        }
    }
    #pragma unroll
    for (int j = 0; j < 4; j++) {
        int t = ti + 16*j;
        float bv  = bs[t];
        float obv = 1.f - bv;
        size_t base = ((size_t)b * T_ + t) * H_ + hc + hi*8;
        float4 s0 = *(const float4*)&s_t[base];
        float4 s1 = *(const float4*)&s_t[base + 4];
        float4 o0, o1;
        o0.x = fmaf(bv, s0.x, obv * acc0[j].x);
        o0.y = fmaf(bv, s0.y, obv * acc0[j].y);
        o0.z = fmaf(bv, s0.z, obv * acc0[j].z);
        o0.w = fmaf(bv, s0.w, obv * acc0[j].w);
        o1.x = fmaf(bv, s1.x, obv * acc1[j].x);
        o1.y = fmaf(bv, s1.y, obv * acc1[j].y);
        o1.z = fmaf(bv, s1.z, obv * acc1[j].z);
        o1.w = fmaf(bv, s1.w, obv * acc1[j].w);
        *(float4*)&out[base]     = o0;
        *(float4*)&out[base + 4] = o1;
    }
}

extern "C" void kernel_launch(void* const* d_in, const int* in_sizes, int n_in,
                              void* d_out, int out_size)
{
    (void)in_sizes; (void)n_in; (void)out_size;
    const float* V   = (const float*)d_in[0];   // (B,K,H)
    const float* h_t = (const float*)d_in[1];   // (B,T,H)
    const float* s_t = (const float*)d_in[2];   // (B,T,H)
    const float* Wv  = (const float*)d_in[3];   // (K,H)
    const float* Wg  = (const float*)d_in[4];   // (K,H)
    const float* Ws  = (const float*)d_in[5];   // (K,H)
    const float* Wh  = (const float*)d_in[6];   // (1,K)

    float* out       = (float*)d_out;
    float* out_chat  = out;                 // (B,T,H)
    float* out_alpha = out + BTH;           // (B,T,K)
    float* out_beta  = out + BTH + BTK;     // (B,T,1)

    rowgemm_cv_kernel<<<BK / TILE_M, 128>>>(V, Wv);          // 196 blocks
    rowgemm_cg_kernel<<<BT / TILE_M, 128>>>(h_t, Wg);        // 256 blocks
    cs_zext_kernel<<<BT / TILE_M, 128>>>(s_t, Ws, Wh);       // 256 blocks
    zsoft_kernel<<<B_, 256>>>(Wh, out_alpha, out_beta);      // 256 blocks
    chat_kernel<<<dim3(H_ / 128, B_), 256>>>(V, s_t, out_alpha, out_beta, out_chat);
}

// round 2
// speedup vs baseline: 1.0709x; 1.0709x over previous
#include <cuda_runtime.h>
#include <cstdint>

// Problem dims
#define B_  256
#define T_  64
#define K_  49
#define H_  512
#define A_  49
#define BT  (B_ * T_)            // 16384
#define BK  (B_ * K_)            // 12544
#define BTH ((size_t)BT * H_)    // 8388608
#define BTK ((size_t)BT * K_)    // 802816

// Scratch (device globals; no allocations allowed)
__device__ float g_cv[B_ * K_ * A_];    // content_v  [b,k,a]
__device__ float g_cg[B_ * T_ * A_];    // content_g  [b,t,a]
__device__ float g_cs[B_ * T_ * A_];    // s_t@Ws^T   [b,t,a] (raw, cg NOT added)

__device__ __forceinline__ float tanh_approx(float x) {
    float y;
    asm("tanh.approx.f32 %0, %1;" : "=f"(y) : "f"(x));
    return y;
}

typedef unsigned long long u64;

__device__ __forceinline__ u64 fma2(u64 a, u64 b, u64 c) {
    u64 d;
    asm("fma.rn.f32x2 %0, %1, %2, %3;" : "=l"(d) : "l"(a), "l"(b), "l"(c));
    return d;
}
__device__ __forceinline__ u64 add2(u64 a, u64 b) {
    u64 d;
    asm("add.rn.f32x2 %0, %1, %2;" : "=l"(d) : "l"(a), "l"(b));
    return d;
}
__device__ __forceinline__ u64 pack2(float lo, float hi) {
    u64 d;
    asm("mov.b64 %0, {%1, %2};" : "=l"(d) : "f"(lo), "f"(hi));
    return d;
}
__device__ __forceinline__ float2 unpack2(u64 v) {
    float2 r;
    asm("mov.b64 {%0, %1}, %2;" : "=f"(r.x), "=f"(r.y) : "l"(v));
    return r;
}

union F4U2 { float4 f4; u64 u[2]; };

// ---------------------------------------------------------------------------
// Merged content GEMM: out[m][a] = sum_h X[m][h] * W[a][h]
//   segment 0: 196 blocks  V    @ Wv -> g_cv   (M = 12544)
//   segment 1: 256 blocks  h_t  @ Wg -> g_cg   (M = 16384)
//   segment 2: 256 blocks  s_t  @ Ws -> g_cs   (M = 16384)
// 256 threads: hh = tid>>7 selects H-half [hh*256, hh*256+256).
// Within half: 16 m-threads (4 rows each) x 8 a-threads (7 a each, q==7 idle).
// Packed f32x2 accumulators; halves reduced through smem at the end.
// ---------------------------------------------------------------------------
#define TILE_M 64
#define XP 68
#define WP 68

__global__ __launch_bounds__(256)
void gemm3_kernel(const float* __restrict__ V,   const float* __restrict__ h_t,
                  const float* __restrict__ s_t, const float* __restrict__ Wv,
                  const float* __restrict__ Wg,  const float* __restrict__ Ws_)
{
    __shared__ __align__(16) float Xs[2][TILE_M][XP];
    __shared__ __align__(16) float Wsm[2][56][WP];   // padded 49->56 rows

    const float* X; const float* W; float* out; int row0;
    int bid = blockIdx.x;
    if (bid < 196)      { X = V;   W = Wv;  out = g_cv; row0 = bid * TILE_M; }
    else if (bid < 452) { X = h_t; W = Wg;  out = g_cg; row0 = (bid - 196) * TILE_M; }
    else                { X = s_t; W = Ws_; out = g_cs; row0 = (bid - 452) * TILE_M; }

    const int tid = threadIdx.x;
    const int hh  = tid >> 7;          // H half
    const int loc = tid & 127;
    const int q   = loc & 7;
    const int mth = loc >> 3;

    u64 acc[4][7];
    #pragma unroll
    for (int i = 0; i < 4; i++)
        #pragma unroll
        for (int j = 0; j < 7; j++) acc[i][j] = 0ull;

    for (int s = 0; s < 4; s++) {
        __syncthreads();
        // Load both halves' tiles: X 2x(64x16 f4), W 2x(49x16 f4)
        for (int idx = tid; idx < 2048; idx += 256) {
            int h2 = idx >> 10, r = (idx >> 4) & 63, c = idx & 15;
            *(float4*)&Xs[h2][r][c*4] =
                *(const float4*)&X[(size_t)(row0 + r) * H_ + h2*256 + s*64 + c*4];
        }
        for (int idx = tid; idx < 1568; idx += 256) {
            int h2 = idx / 784, j = idx % 784;
            int r = j >> 4, c = j & 15;
            *(float4*)&Wsm[h2][r][c*4] =
                *(const float4*)&W[(size_t)r * H_ + h2*256 + s*64 + c*4];
        }
        __syncthreads();

        #pragma unroll
        for (int h4 = 0; h4 < 16; h4++) {
            F4U2 w[7];
            #pragma unroll
            for (int j = 0; j < 7; j++)
                w[j].f4 = *(const float4*)&Wsm[hh][q*7 + j][h4*4];
            #pragma unroll
            for (int i = 0; i < 4; i++) {
                F4U2 x;
                x.f4 = *(const float4*)&Xs[hh][mth*4 + i][h4*4];
                #pragma unroll
                for (int j = 0; j < 7; j++) {
                    acc[i][j] = fma2(x.u[0], w[j].u[0], acc[i][j]);
                    acc[i][j] = fma2(x.u[1], w[j].u[1], acc[i][j]);
                }
            }
        }
    }

    // cross-half reduction through smem (reuse Xs: 3584 u64 = 28KB <= 34.8KB)
    __syncthreads();
    u64* red = (u64*)&Xs[0][0][0];
    if (hh == 1) {
        #pragma unroll
        for (int i = 0; i < 4; i++)
            #pragma unroll
            for (int j = 0; j < 7; j++)
                red[loc * 28 + i*7 + j] = acc[i][j];
    }
    __syncthreads();
    if (hh == 0 && q < 7) {
        #pragma unroll
        for (int i = 0; i < 4; i++) {
            int m = row0 + mth*4 + i;
            #pragma unroll
            for (int j = 0; j < 7; j++) {
                u64 t = add2(acc[i][j], red[loc * 28 + i*7 + j]);
                float2 f = unpack2(t);
                out[(size_t)m * A_ + q*7 + j] = f.x + f.y;
            }
        }
    }
}

// ---------------------------------------------------------------------------
// zsoft: z_t + z_ext + softmax(alpha) + extended softmax(beta).
// Grid (2, B): block handles 32 t-rows of one batch. 256 threads.
// ---------------------------------------------------------------------------
#define TZ 32

__global__ __launch_bounds__(256)
void zsoft_kernel(const float* __restrict__ Wh,
                  float* __restrict__ out_alpha, float* __restrict__ out_beta)
{
    const int b  = blockIdx.y;
    const int t0 = blockIdx.x * TZ;
    __shared__ float cvs[K_ * 50];
    __shared__ float cgs[TZ * 50];
    __shared__ float css[TZ * 50];
    __shared__ float whs[A_];
    __shared__ float zes[TZ];
    __shared__ float zs[TZ * 50];
    const int tid = threadIdx.x;

    for (int i = tid; i < K_ * A_; i += 256)
        cvs[(i / A_) * 50 + (i % A_)] = g_cv[(size_t)b * K_ * A_ + i];
    for (int i = tid; i < TZ * A_; i += 256) {
        size_t src = ((size_t)b * T_ + t0) * A_ + i;
        cgs[(i / A_) * 50 + (i % A_)] = g_cg[src];
        css[(i / A_) * 50 + (i % A_)] = g_cs[src];
    }
    if (tid < A_) whs[tid] = Wh[tid];
    __syncthreads();

    // items 0..TZ*K-1 : z_t ;  items TZ*K..TZ*K+TZ-1 : z_ext
    for (int item = tid; item < TZ * K_ + TZ; item += 256) {
        const float* rowA;
        const float* rowB;
        if (item < TZ * K_) {
            int t = item / K_, k = item % K_;
            rowA = &cgs[t * 50];
            rowB = &cvs[k * 50];
        } else {
            int t = item - TZ * K_;
            rowA = &cgs[t * 50];
            rowB = &css[t * 50];
        }
        float s0 = 0.f, s1 = 0.f;
        #pragma unroll
        for (int a = 0; a < 48; a += 2) {
            s0 = fmaf(tanh_approx(rowA[a]   + rowB[a]),   whs[a],   s0);
            s1 = fmaf(tanh_approx(rowA[a+1] + rowB[a+1]), whs[a+1], s1);
        }
        s0 = fmaf(tanh_approx(rowA[48] + rowB[48]), whs[48], s0);
        float z = s0 + s1;
        if (item < TZ * K_) {
            int t = item / K_, k = item % K_;
            zs[t * 50 + k] = z;
        } else {
            zes[item - TZ * K_] = z;
        }
    }
    __syncthreads();

    const int warp = tid >> 5, lane = tid & 31;
    for (int t = warp; t < TZ; t += 8) {
        float z1 = (lane < K_)      ? zs[t*50 + lane]      : -1e30f;
        float z2 = (lane + 32 < K_) ? zs[t*50 + lane + 32] : -1e30f;
        float m = fmaxf(z1, z2);
        #pragma unroll
        for (int o = 16; o; o >>= 1) m = fmaxf(m, __shfl_xor_sync(0xffffffffu, m, o));
        float e1 = (lane < K_)      ? __expf(z1 - m) : 0.f;
        float e2 = (lane + 32 < K_) ? __expf(z2 - m) : 0.f;
        float s = e1 + e2;
        #pragma unroll
        for (int o = 16; o; o >>= 1) s += __shfl_xor_sync(0xffffffffu, s, o);
        float inv = 1.f / s;
        size_t bt = (size_t)b * T_ + t0 + t;
        if (lane < K_)      out_alpha[bt * K_ + lane]      = e1 * inv;
        if (lane + 32 < K_) out_alpha[bt * K_ + lane + 32] = e2 * inv;
        if (lane == 0) {
            float ze = zes[t];
            float m2 = fmaxf(m, ze);
            float ee = __expf(ze - m2);
            float denom = s * __expf(m - m2) + ee;
            out_beta[bt] = ee / denom;
        }
    }
}

// ---------------------------------------------------------------------------
// c_hat = beta*s_t + (1-beta)*(alpha @ V).  Block: (h-chunk of 128, b).
// 256 threads = 16 h-threads x 16 t-threads; thread: 4 t x 8 h, packed f32x2.
// ---------------------------------------------------------------------------
__global__ __launch_bounds__(256)
void chat_kernel(const float* __restrict__ V, const float* __restrict__ s_t,
                 const float* __restrict__ alpha, const float* __restrict__ beta,
                 float* __restrict__ out)
{
    const int b  = blockIdx.y;
    const int hc = blockIdx.x * 128;
    __shared__ __align__(16) float Vs[K_ * 128];
    __shared__ float as[T_ * 51];
    __shared__ float bs[T_];
    const int tid = threadIdx.x;

    for (int idx = tid; idx < K_ * 32; idx += 256) {
        int k = idx >> 5, c = idx & 31;
        *(float4*)&Vs[k * 128 + c*4] =
            *(const float4*)&V[((size_t)b * K_ + k) * H_ + hc + c*4];
    }
    for (int i = tid; i < T_ * K_; i += 256)
        as[(i / K_) * 51 + (i % K_)] = alpha[(size_t)b * T_ * K_ + i];
    if (tid < T_) bs[tid] = beta[(size_t)b * T_ + tid];
    __syncthreads();

    const int hi = tid & 15, ti = tid >> 4;
    u64 acc[4][4];
    #pragma unroll
    for (int j = 0; j < 4; j++)
        #pragma unroll
        for (int p = 0; p < 4; p++) acc[j][p] = 0ull;

    for (int k = 0; k < K_; k++) {
        F4U2 v0, v1;
        v0.f4 = *(const float4*)&Vs[k * 128 + hi*8];
        v1.f4 = *(const float4*)&Vs[k * 128 + hi*8 + 4];
        #pragma unroll
        for (int j = 0; j < 4; j++) {
            float a = as[(ti + 16*j) * 51 + k];
            u64 a2 = pack2(a, a);
            acc[j][0] = fma2(a2, v0.u[0], acc[j][0]);
            acc[j][1] = fma2(a2, v0.u[1], acc[j][1]);
            acc[j][2] = fma2(a2, v1.u[0], acc[j][2]);
            acc[j][3] = fma2(a2, v1.u[1], acc[j][3]);
        }
    }
    #pragma unroll
    for (int j = 0; j < 4; j++) {
        int t = ti + 16*j;
        float bv  = bs[t];
        float obv = 1.f - bv;
        size_t base = ((size_t)b * T_ + t) * H_ + hc + hi*8;
        float4 s0 = *(const float4*)&s_t[base];
        float4 s1 = *(const float4*)&s_t[base + 4];
        float2 c0 = unpack2(acc[j][0]);
        float2 c1 = unpack2(acc[j][1]);
        float2 c2 = unpack2(acc[j][2]);
        float2 c3 = unpack2(acc[j][3]);
        float4 o0, o1;
        o0.x = fmaf(bv, s0.x, obv * c0.x);
        o0.y = fmaf(bv, s0.y, obv * c0.y);
        o0.z = fmaf(bv, s0.z, obv * c1.x);
        o0.w = fmaf(bv, s0.w, obv * c1.y);
        o1.x = fmaf(bv, s1.x, obv * c2.x);
        o1.y = fmaf(bv, s1.y, obv * c2.y);
        o1.z = fmaf(bv, s1.z, obv * c3.x);
        o1.w = fmaf(bv, s1.w, obv * c3.y);
        *(float4*)&out[base]     = o0;
        *(float4*)&out[base + 4] = o1;
    }
}

extern "C" void kernel_launch(void* const* d_in, const int* in_sizes, int n_in,
                              void* d_out, int out_size)
{
    (void)in_sizes; (void)n_in; (void)out_size;
    const float* V   = (const float*)d_in[0];   // (B,K,H)
    const float* h_t = (const float*)d_in[1];   // (B,T,H)
    const float* s_t = (const float*)d_in[2];   // (B,T,H)
    const float* Wv  = (const float*)d_in[3];   // (K,H)
    const float* Wg  = (const float*)d_in[4];   // (K,H)
    const float* Ws_ = (const float*)d_in[5];   // (K,H)
    const float* Wh  = (const float*)d_in[6];   // (1,K)

    float* out       = (float*)d_out;
    float* out_chat  = out;                 // (B,T,H)
    float* out_alpha = out + BTH;           // (B,T,K)
    float* out_beta  = out + BTH + BTK;     // (B,T,1)

    gemm3_kernel<<<708, 256>>>(V, h_t, s_t, Wv, Wg, Ws_);
    zsoft_kernel<<<dim3(2, B_), 256>>>(Wh, out_alpha, out_beta);
    chat_kernel<<<dim3(H_ / 128, B_), 256>>>(V, s_t, out_alpha, out_beta, out_chat);
}

// round 3
// speedup vs baseline: 1.3356x; 1.2472x over previous
#include <cuda_runtime.h>
#include <cstdint>

// Problem dims
#define B_  256
#define T_  64
#define K_  49
#define H_  512
#define A_  49
#define BT  (B_ * T_)            // 16384
#define BK  (B_ * K_)            // 12544
#define BTH ((size_t)BT * H_)    // 8388608
#define BTK ((size_t)BT * K_)    // 802816
#define CP  52                   // padded row pitch for scratch [*, 52]

// Scratch (device globals; no allocations allowed)
__device__ float g_cv[B_ * K_ * CP];    // content_v  [b,k,52]
__device__ float g_cg[B_ * T_ * CP];    // content_g  [b,t,52]
__device__ float g_cs[B_ * T_ * CP];    // s_t@Ws^T   [b,t,52] (raw, cg NOT added)

__device__ __forceinline__ float tanh_approx(float x) {
    float y;
    asm("tanh.approx.f32 %0, %1;" : "=f"(y) : "f"(x));
    return y;
}

typedef unsigned long long u64;

__device__ __forceinline__ u64 fma2(u64 a, u64 b, u64 c) {
    u64 d;
    asm("fma.rn.f32x2 %0, %1, %2, %3;" : "=l"(d) : "l"(a), "l"(b), "l"(c));
    return d;
}
__device__ __forceinline__ u64 pack2(float lo, float hi) {
    u64 d;
    asm("mov.b64 %0, {%1, %2};" : "=l"(d) : "f"(lo), "f"(hi));
    return d;
}
__device__ __forceinline__ float2 unpack2(u64 v) {
    float2 r;
    asm("mov.b64 {%0, %1}, %2;" : "=f"(r.x), "=f"(r.y) : "l"(v));
    return r;
}

union F4U2 { float4 f4; u64 u[2]; };

// ---------------------------------------------------------------------------
// Merged content GEMM: out[m][a] = sum_h X[m][h] * W[a][h]
//   seg 0:  98 blocks  V    @ Wv -> g_cv
//   seg 1: 128 blocks  h_t  @ Wg -> g_cg
//   seg 2: 128 blocks  s_t  @ Ws -> g_cs
// TILE_M=128, 224 threads = 7 warps; warp w owns a-cols [7w, 7w+7).
// Thread: 4 m-rows (mth, mth+32, mth+64, mth+96) x 7 a, f32x2 packed acc,
// full K=512 accumulated in registers (8 chunks of 64).
// Xs is XOR-swizzled so 32-distinct-row f4 reads are bank-conflict-free;
// Ws reads are warp-wide broadcasts.
// ---------------------------------------------------------------------------
#define TM 128
#define NTG 224

__global__ __launch_bounds__(NTG, 2)
void gemm3_kernel(const float* __restrict__ V,   const float* __restrict__ h_t,
                  const float* __restrict__ s_t, const float* __restrict__ Wv,
                  const float* __restrict__ Wg,  const float* __restrict__ Ws_)
{
    __shared__ __align__(16) float Xs[TM][64];
    __shared__ __align__(16) float Wsm[A_][68];

    const float* X; const float* W; float* out; int row0;
    const int bid = blockIdx.x;
    if (bid < 98)       { X = V;   W = Wv;  out = g_cv; row0 = bid * TM; }
    else if (bid < 226) { X = h_t; W = Wg;  out = g_cg; row0 = (bid - 98) * TM; }
    else                { X = s_t; W = Ws_; out = g_cs; row0 = (bid - 226) * TM; }

    const int tid = threadIdx.x;
    const int q   = tid >> 5;       // warp id = a-group (0..6)
    const int mth = tid & 31;

    u64 acc[4][7];
    #pragma unroll
    for (int i = 0; i < 4; i++)
        #pragma unroll
        for (int j = 0; j < 7; j++) acc[i][j] = 0ull;

    for (int s = 0; s < 8; s++) {
        __syncthreads();
        // X tile: 128 rows x 16 f4, XOR-swizzled slot = c4 ^ (r & 7)
        for (int idx = tid; idx < TM * 16; idx += NTG) {
            int r = idx >> 4, c4 = idx & 15;
            float4 v = *(const float4*)&X[(size_t)(row0 + r) * H_ + s*64 + c4*4];
            *(float4*)&Xs[r][(c4 ^ (r & 7)) * 4] = v;
        }
        // W tile: 49 rows x 16 f4, plain
        for (int idx = tid; idx < A_ * 16; idx += NTG) {
            int r = idx >> 4, c4 = idx & 15;
            float4 v = *(const float4*)&W[(size_t)r * H_ + s*64 + c4*4];
            *(float4*)&Wsm[r][c4*4] = v;
        }
        __syncthreads();

        #pragma unroll
        for (int h4 = 0; h4 < 16; h4++) {
            F4U2 w[7];
            #pragma unroll
            for (int j = 0; j < 7; j++)
                w[j].f4 = *(const float4*)&Wsm[q*7 + j][h4*4];   // broadcast
            #pragma unroll
            for (int i = 0; i < 4; i++) {
                int row = mth + 32*i;
                F4U2 x;
                x.f4 = *(const float4*)&Xs[row][((h4 ^ (row & 7))) * 4];
                #pragma unroll
                for (int j = 0; j < 7; j++) {
                    acc[i][j] = fma2(x.u[0], w[j].u[0], acc[i][j]);
                    acc[i][j] = fma2(x.u[1], w[j].u[1], acc[i][j]);
                }
            }
        }
    }

    // Epilogue: stage [128][52] in smem (reuse Xs), then coalesced f4 stores.
    __syncthreads();
    float* St = &Xs[0][0];
    #pragma unroll
    for (int i = 0; i < 4; i++) {
        int row = mth + 32*i;
        #pragma unroll
        for (int j = 0; j < 7; j++) {
            float2 f = unpack2(acc[i][j]);
            St[row * CP + q*7 + j] = f.x + f.y;
        }
    }
    __syncthreads();
    for (int idx = tid; idx < TM * 13; idx += NTG) {
        int r = idx / 13, c4 = idx % 13;
        *(float4*)&out[(size_t)(row0 + r) * CP + c4*4] =
            *(const float4*)&St[r * CP + c4*4];
    }
}

// ---------------------------------------------------------------------------
// zsoft: z_t + z_ext + softmax(alpha) + extended softmax(beta).
// Grid (2, B): block handles 32 t-rows of one batch. 256 threads.
// smem pitch 53 (odd) -> conflict-free scalar reads across k.
// ---------------------------------------------------------------------------
#define TZ 32
#define ZP 53

__global__ __launch_bounds__(256)
void zsoft_kernel(const float* __restrict__ Wh,
                  float* __restrict__ out_alpha, float* __restrict__ out_beta)
{
    const int b  = blockIdx.y;
    const int t0 = blockIdx.x * TZ;
    __shared__ float cvs[K_ * ZP];
    __shared__ float cgs[TZ * ZP];
    __shared__ float css[TZ * ZP];
    __shared__ float whs[A_];
    __shared__ float zes[TZ];
    __shared__ float zs[TZ * 50];
    const int tid = threadIdx.x;

    for (int i = tid; i < K_ * A_; i += 256) {
        int k = i / A_, a = i % A_;
        cvs[k * ZP + a] = g_cv[((size_t)b * K_ + k) * CP + a];
    }
    for (int i = tid; i < TZ * A_; i += 256) {
        int t = i / A_, a = i % A_;
        size_t src = ((size_t)b * T_ + t0 + t) * CP + a;
        cgs[t * ZP + a] = g_cg[src];
        css[t * ZP + a] = g_cs[src];
    }
    if (tid < A_) whs[tid] = Wh[tid];
    __syncthreads();

    // items 0..TZ*K-1 : z_t ;  items TZ*K..TZ*K+TZ-1 : z_ext
    for (int item = tid; item < TZ * K_ + TZ; item += 256) {
        const float* rowA;
        const float* rowB;
        if (item < TZ * K_) {
            int t = item / K_, k = item % K_;
            rowA = &cgs[t * ZP];
            rowB = &cvs[k * ZP];
        } else {
            int t = item - TZ * K_;
            rowA = &cgs[t * ZP];
            rowB = &css[t * ZP];
        }
        float s0 = 0.f, s1 = 0.f;
        #pragma unroll
        for (int a = 0; a < 48; a += 2) {
            s0 = fmaf(tanh_approx(rowA[a]   + rowB[a]),   whs[a],   s0);
            s1 = fmaf(tanh_approx(rowA[a+1] + rowB[a+1]), whs[a+1], s1);
        }
        s0 = fmaf(tanh_approx(rowA[48] + rowB[48]), whs[48], s0);
        float z = s0 + s1;
        if (item < TZ * K_) {
            int t = item / K_, k = item % K_;
            zs[t * 50 + k] = z;
        } else {
            zes[item - TZ * K_] = z;
        }
    }
    __syncthreads();

    const int warp = tid >> 5, lane = tid & 31;
    for (int t = warp; t < TZ; t += 8) {
        float z1 = (lane < K_)      ? zs[t*50 + lane]      : -1e30f;
        float z2 = (lane + 32 < K_) ? zs[t*50 + lane + 32] : -1e30f;
        float m = fmaxf(z1, z2);
        #pragma unroll
        for (int o = 16; o; o >>= 1) m = fmaxf(m, __shfl_xor_sync(0xffffffffu, m, o));
        float e1 = (lane < K_)      ? __expf(z1 - m) : 0.f;
        float e2 = (lane + 32 < K_) ? __expf(z2 - m) : 0.f;
        float s = e1 + e2;
        #pragma unroll
        for (int o = 16; o; o >>= 1) s += __shfl_xor_sync(0xffffffffu, s, o);
        float inv = 1.f / s;
        size_t bt = (size_t)b * T_ + t0 + t;
        if (lane < K_)      out_alpha[bt * K_ + lane]      = e1 * inv;
        if (lane + 32 < K_) out_alpha[bt * K_ + lane + 32] = e2 * inv;
        if (lane == 0) {
            float ze = zes[t];
            float m2 = fmaxf(m, ze);
            float ee = __expf(ze - m2);
            float denom = s * __expf(m - m2) + ee;
            out_beta[bt] = ee / denom;
        }
    }
}

// ---------------------------------------------------------------------------
// c_hat = beta*s_t + (1-beta)*(alpha @ V).  Block: (h-chunk of 128, b).
// 256 threads = 16 h-threads x 16 t-threads; thread: 4 t x 8 h, packed f32x2.
// ---------------------------------------------------------------------------
__global__ __launch_bounds__(256)
void chat_kernel(const float* __restrict__ V, const float* __restrict__ s_t,
                 const float* __restrict__ alpha, const float* __restrict__ beta,
                 float* __restrict__ out)
{
    const int b  = blockIdx.y;
    const int hc = blockIdx.x * 128;
    __shared__ __align__(16) float Vs[K_ * 128];
    __shared__ float as[T_ * 51];
    __shared__ float bs[T_];
    const int tid = threadIdx.x;

    for (int idx = tid; idx < K_ * 32; idx += 256) {
        int k = idx >> 5, c = idx & 31;
        *(float4*)&Vs[k * 128 + c*4] =
            *(const float4*)&V[((size_t)b * K_ + k) * H_ + hc + c*4];
    }
    for (int i = tid; i < T_ * K_; i += 256)
        as[(i / K_) * 51 + (i % K_)] = alpha[(size_t)b * T_ * K_ + i];
    if (tid < T_) bs[tid] = beta[(size_t)b * T_ + tid];
    __syncthreads();

    const int hi = tid & 15, ti = tid >> 4;
    u64 acc[4][4];
    #pragma unroll
    for (int j = 0; j < 4; j++)
        #pragma unroll
        for (int p = 0; p < 4; p++) acc[j][p] = 0ull;

    for (int k = 0; k < K_; k++) {
        F4U2 v0, v1;
        v0.f4 = *(const float4*)&Vs[k * 128 + hi*8];
        v1.f4 = *(const float4*)&Vs[k * 128 + hi*8 + 4];
        #pragma unroll
        for (int j = 0; j < 4; j++) {
            float a = as[(ti + 16*j) * 51 + k];
            u64 a2 = pack2(a, a);
            acc[j][0] = fma2(a2, v0.u[0], acc[j][0]);
            acc[j][1] = fma2(a2, v0.u[1], acc[j][1]);
            acc[j][2] = fma2(a2, v1.u[0], acc[j][2]);
            acc[j][3] = fma2(a2, v1.u[1], acc[j][3]);
        }
    }
    #pragma unroll
    for (int j = 0; j < 4; j++) {
        int t = ti + 16*j;
        float bv  = bs[t];
        float obv = 1.f - bv;
        size_t base = ((size_t)b * T_ + t) * H_ + hc + hi*8;
        float4 s0 = *(const float4*)&s_t[base];
        float4 s1 = *(const float4*)&s_t[base + 4];
        float2 c0 = unpack2(acc[j][0]);
        float2 c1 = unpack2(acc[j][1]);
        float2 c2 = unpack2(acc[j][2]);
        float2 c3 = unpack2(acc[j][3]);
        float4 o0, o1;
        o0.x = fmaf(bv, s0.x, obv * c0.x);
        o0.y = fmaf(bv, s0.y, obv * c0.y);
        o0.z = fmaf(bv, s0.z, obv * c1.x);
        o0.w = fmaf(bv, s0.w, obv * c1.y);
        o1.x = fmaf(bv, s1.x, obv * c2.x);
        o1.y = fmaf(bv, s1.y, obv * c2.y);
        o1.z = fmaf(bv, s1.z, obv * c3.x);
        o1.w = fmaf(bv, s1.w, obv * c3.y);
        *(float4*)&out[base]     = o0;
        *(float4*)&out[base + 4] = o1;
    }
}

extern "C" void kernel_launch(void* const* d_in, const int* in_sizes, int n_in,
                              void* d_out, int out_size)
{
    (void)in_sizes; (void)n_in; (void)out_size;
    const float* V   = (const float*)d_in[0];   // (B,K,H)
    const float* h_t = (const float*)d_in[1];   // (B,T,H)
    const float* s_t = (const float*)d_in[2];   // (B,T,H)
    const float* Wv  = (const float*)d_in[3];   // (K,H)
    const float* Wg  = (const float*)d_in[4];   // (K,H)
    const float* Ws_ = (const float*)d_in[5];   // (K,H)
    const float* Wh  = (const float*)d_in[6];   // (1,K)

    float* out       = (float*)d_out;
    float* out_chat  = out;                 // (B,T,H)
    float* out_alpha = out + BTH;           // (B,T,K)
    float* out_beta  = out + BTH + BTK;     // (B,T,1)

    gemm3_kernel<<<354, NTG>>>(V, h_t, s_t, Wv, Wg, Ws_);
    zsoft_kernel<<<dim3(2, B_), 256>>>(Wh, out_alpha, out_beta);
    chat_kernel<<<dim3(H_ / 128, B_), 256>>>(V, s_t, out_alpha, out_beta, out_chat);
}

// round 5
// speedup vs baseline: 2.0951x; 1.5686x over previous
#include <cuda_runtime.h>
#include <cstdint>

// Problem dims
#define B_  256
#define T_  64
#define K_  49
#define H_  512
#define A_  49
#define BT  (B_ * T_)            // 16384
#define BK  (B_ * K_)            // 12544
#define BTH ((size_t)BT * H_)    // 8388608
#define BTK ((size_t)BT * K_)    // 802816
#define CP  52                   // padded row pitch for scratch [*, 52]

// Scratch (device globals; no allocations allowed)
__device__ __align__(16) float g_cv[B_ * K_ * CP];   // content_v  [b,k,52]
__device__ __align__(16) float g_cg[B_ * T_ * CP];   // content_g  [b,t,52]
__device__ __align__(16) float g_cs[B_ * T_ * CP];   // s_t@Ws^T   [b,t,52]
__device__ __align__(16) float g_Wp[3 * 32768];      // permuted W fragments

typedef unsigned long long u64;

__device__ __forceinline__ float tanh_approx(float x) {
    float y;
    asm("tanh.approx.f32 %0, %1;" : "=f"(y) : "f"(x));
    return y;
}
__device__ __forceinline__ u64 fma2(u64 a, u64 b, u64 c) {
    u64 d;
    asm("fma.rn.f32x2 %0, %1, %2, %3;" : "=l"(d) : "l"(a), "l"(b), "l"(c));
    return d;
}
__device__ __forceinline__ u64 pack2(float lo, float hi) {
    u64 d;
    asm("mov.b64 %0, {%1, %2};" : "=l"(d) : "f"(lo), "f"(hi));
    return d;
}
__device__ __forceinline__ float2 unpack2(u64 v) {
    float2 r;
    asm("mov.b64 {%0, %1}, %2;" : "=f"(r.x), "=f"(r.y) : "l"(v));
    return r;
}
union F4U2 { float4 f4; u64 u[2]; };

__device__ __forceinline__ uint32_t s2u(const void* p) {
    uint32_t a;
    asm("{ .reg .u64 t; cvta.to.shared.u64 t, %1; cvt.u32.u64 %0, t; }"
        : "=r"(a) : "l"(p));
    return a;
}
__device__ __forceinline__ void cpa16(uint32_t dst, const void* src) {
    asm volatile("cp.async.cg.shared.global [%0], [%1], 16;"
                 :: "r"(dst), "l"(src) : "memory");
}
__device__ __forceinline__ void mma_tf32(float* d,
                                         float a0, float a1, float a2, float a3,
                                         float b0, float b1) {
    asm volatile(
        "mma.sync.aligned.m16n8k8.row.col.f32.tf32.tf32.f32 "
        "{%0,%1,%2,%3}, {%4,%5,%6,%7}, {%8,%9}, {%0,%1,%2,%3};"
        : "+f"(d[0]), "+f"(d[1]), "+f"(d[2]), "+f"(d[3])
        : "r"(__float_as_uint(a0)), "r"(__float_as_uint(a1)),
          "r"(__float_as_uint(a2)), "r"(__float_as_uint(a3)),
          "r"(__float_as_uint(b0)), "r"(__float_as_uint(b1)));
}

// ---------------------------------------------------------------------------
// Permute W matrices into mma.sync B-fragment order.
// Wp[mat] layout (float4 units): idx4 = (S*4 + j)*32 + lane, S = kstep 0..63.
//   g=lane>>2, tg=lane&3, k=S*8+tg, r0=16j+g, r1=r0+8:
//   F = (W[r0][k], W[r0][k+4], W[r1][k], W[r1][k+4]), 0 when row>=49.
// ---------------------------------------------------------------------------
__global__ __launch_bounds__(128)
void wperm_kernel(const float* __restrict__ Wv, const float* __restrict__ Wg,
                  const float* __restrict__ Ws_)
{
    int tid = blockIdx.x * 128 + threadIdx.x;       // 0..24575
    int mat = tid / 8192;
    int rem = tid % 8192;
    int S   = rem / 128;
    int j   = (rem / 32) % 4;
    int l   = rem % 32;
    int g = l >> 2, tg = l & 3;
    int k = S * 8 + tg;
    int r0 = 16 * j + g, r1 = r0 + 8;
    const float* W = (mat == 0) ? Wv : (mat == 1) ? Wg : Ws_;
    float4 F;
    F.x = (r0 < A_) ? W[(size_t)r0 * H_ + k]     : 0.f;
    F.y = (r0 < A_) ? W[(size_t)r0 * H_ + k + 4] : 0.f;
    F.z = (r1 < A_) ? W[(size_t)r1 * H_ + k]     : 0.f;
    F.w = (r1 < A_) ? W[(size_t)r1 * H_ + k + 4] : 0.f;
    *(float4*)&g_Wp[(size_t)mat * 32768 + (size_t)rem * 4] = F;
}

// ---------------------------------------------------------------------------
// tf32 mma.sync content GEMM: out[m][a] = sum_h X[m][h] * W[a][h]
//   seg 0: 196 blocks  V    -> g_cv ; seg 1: 256 blocks h_t -> g_cg ;
//   seg 2: 256 blocks  s_t  -> g_cs
// CTA: 128 thr (4 warps), tile M=64 x N=64, K in 8 chunks of 64.
// Warp: 16 rows x 64 cols = 8 x m16n8k8.
// ---------------------------------------------------------------------------
__global__ __launch_bounds__(128, 3)
void gemm_mma_kernel(const float* __restrict__ V,   const float* __restrict__ h_t,
                     const float* __restrict__ s_t)
{
    __shared__ __align__(16) float  Xs[64][68];
    __shared__ __align__(16) float4 Bs[1024];       // [s][j][lane]

    const float* X; const float* wp; float* out; int row0;
    const int bid = blockIdx.x;
    if (bid < 196)      { X = V;   wp = g_Wp;          out = g_cv; row0 = bid * 64; }
    else if (bid < 452) { X = h_t; wp = g_Wp + 32768;  out = g_cg; row0 = (bid - 196) * 64; }
    else                { X = s_t; wp = g_Wp + 65536;  out = g_cs; row0 = (bid - 452) * 64; }

    const int tid  = threadIdx.x;
    const int wid  = tid >> 5;
    const int lane = tid & 31;
    const int g    = lane >> 2;
    const int tg   = lane & 3;
    const uint32_t xs_u = s2u(&Xs[0][0]);
    const uint32_t bs_u = s2u(&Bs[0]);

    float acc[8][4];
    #pragma unroll
    for (int n = 0; n < 8; n++)
        #pragma unroll
        for (int c = 0; c < 4; c++) acc[n][c] = 0.f;

    for (int c = 0; c < 8; c++) {
        __syncthreads();
        // X tile: 64 rows x 16 f4 (cols c*64..c*64+63), pitch 68
        #pragma unroll
        for (int i = 0; i < 8; i++) {
            int idx = tid + i * 128;
            int r = idx >> 4, c4 = idx & 15;
            cpa16(xs_u + (uint32_t)(r * 68 + c4 * 4) * 4,
                  &X[(size_t)(row0 + r) * H_ + c * 64 + c4 * 4]);
        }
        // B chunk: 1024 f4 linear
        #pragma unroll
        for (int i = 0; i < 8; i++) {
            int idx = tid + i * 128;
            cpa16(bs_u + (uint32_t)idx * 16, wp + (size_t)c * 4096 + (size_t)idx * 4);
        }
        asm volatile("cp.async.commit_group;" ::: "memory");
        asm volatile("cp.async.wait_group 0;" ::: "memory");
        __syncthreads();

        #pragma unroll
        for (int s = 0; s < 8; s++) {
            float a0 = Xs[16*wid + g    ][s*8 + tg    ];
            float a1 = Xs[16*wid + g + 8][s*8 + tg    ];
            float a2 = Xs[16*wid + g    ][s*8 + tg + 4];
            float a3 = Xs[16*wid + g + 8][s*8 + tg + 4];
            #pragma unroll
            for (int j = 0; j < 4; j++) {
                float4 bf = Bs[(s*4 + j) * 32 + lane];
                mma_tf32(acc[2*j],     a0, a1, a2, a3, bf.x, bf.y);
                mma_tf32(acc[2*j + 1], a0, a1, a2, a3, bf.z, bf.w);
            }
        }
    }

    // Writeback: D frag (m16n8): c0 (g, 2tg), c1 (g, 2tg+1), c2 (g+8, ...), c3.
    const int r0g = row0 + 16 * wid + g;
    #pragma unroll
    for (int n = 0; n < 8; n++) {
        int col0 = n * 8 + tg * 2;
        if (col0 < CP) {
            *(u64*)&out[(size_t)r0g * CP + col0]       = pack2(acc[n][0], acc[n][1]);
            *(u64*)&out[(size_t)(r0g + 8) * CP + col0] = pack2(acc[n][2], acc[n][3]);
        }
    }
}

// ---------------------------------------------------------------------------
// zsoft: z_t + z_ext + softmax(alpha) + extended softmax(beta).
// Grid (2, B): block handles 32 t-rows of one batch. 256 threads.
// ---------------------------------------------------------------------------
#define TZ 32
#define ZP 53

__global__ __launch_bounds__(256)
void zsoft_kernel(const float* __restrict__ Wh,
                  float* __restrict__ out_alpha, float* __restrict__ out_beta)
{
    const int b  = blockIdx.y;
    const int t0 = blockIdx.x * TZ;
    __shared__ float cvs[K_ * ZP];
    __shared__ float cgs[TZ * ZP];
    __shared__ float css[TZ * ZP];
    __shared__ float whs[A_];
    __shared__ float zes[TZ];
    __shared__ float zs[TZ * 50];
    const int tid = threadIdx.x;

    for (int i = tid; i < K_ * A_; i += 256) {
        int k = i / A_, a = i % A_;
        cvs[k * ZP + a] = g_cv[((size_t)b * K_ + k) * CP + a];
    }
    for (int i = tid; i < TZ * A_; i += 256) {
        int t = i / A_, a = i % A_;
        size_t src = ((size_t)b * T_ + t0 + t) * CP + a;
        cgs[t * ZP + a] = g_cg[src];
        css[t * ZP + a] = g_cs[src];
    }
    if (tid < A_) whs[tid] = Wh[tid];
    __syncthreads();

    for (int item = tid; item < TZ * K_ + TZ; item += 256) {
        const float* rowA;
        const float* rowB;
        if (item < TZ * K_) {
            int t = item / K_, k = item % K_;
            rowA = &cgs[t * ZP];
            rowB = &cvs[k * ZP];
        } else {
            int t = item - TZ * K_;
            rowA = &cgs[t * ZP];
            rowB = &css[t * ZP];
        }
        float s0 = 0.f, s1 = 0.f;
        #pragma unroll
        for (int a = 0; a < 48; a += 2) {
            s0 = fmaf(tanh_approx(rowA[a]   + rowB[a]),   whs[a],   s0);
            s1 = fmaf(tanh_approx(rowA[a+1] + rowB[a+1]), whs[a+1], s1);
        }
        s0 = fmaf(tanh_approx(rowA[48] + rowB[48]), whs[48], s0);
        float z = s0 + s1;
        if (item < TZ * K_) {
            int t = item / K_, k = item % K_;
            zs[t * 50 + k] = z;
        } else {
            zes[item - TZ * K_] = z;
        }
    }
    __syncthreads();

    const int warp = tid >> 5, lane = tid & 31;
    for (int t = warp; t < TZ; t += 8) {
        float z1 = (lane < K_)      ? zs[t*50 + lane]      : -1e30f;
        float z2 = (lane + 32 < K_) ? zs[t*50 + lane + 32] : -1e30f;
        float m = fmaxf(z1, z2);
        #pragma unroll
        for (int o = 16; o; o >>= 1) m = fmaxf(m, __shfl_xor_sync(0xffffffffu, m, o));
        float e1 = (lane < K_)      ? __expf(z1 - m) : 0.f;
        float e2 = (lane + 32 < K_) ? __expf(z2 - m) : 0.f;
        float s = e1 + e2;
        #pragma unroll
        for (int o = 16; o; o >>= 1) s += __shfl_xor_sync(0xffffffffu, s, o);
        float inv = 1.f / s;
        size_t bt = (size_t)b * T_ + t0 + t;
        if (lane < K_)      out_alpha[bt * K_ + lane]      = e1 * inv;
        if (lane + 32 < K_) out_alpha[bt * K_ + lane + 32] = e2 * inv;
        if (lane == 0) {
            float ze = zes[t];
            float m2 = fmaxf(m, ze);
            float ee = __expf(ze - m2);
            float denom = s * __expf(m - m2) + ee;
            out_beta[bt] = ee / denom;
        }
    }
}

// ---------------------------------------------------------------------------
// c_hat = beta*s_t + (1-beta)*(alpha @ V).  Block: (h-chunk of 128, b).
// ---------------------------------------------------------------------------
__global__ __launch_bounds__(256)
void chat_kernel(const float* __restrict__ V, const float* __restrict__ s_t,
                 const float* __restrict__ alpha, const float* __restrict__ beta,
                 float* __restrict__ out)
{
    const int b  = blockIdx.y;
    const int hc = blockIdx.x * 128;
    __shared__ __align__(16) float Vs[K_ * 128];
    __shared__ float as[T_ * 51];
    __shared__ float bs[T_];
    const int tid = threadIdx.x;

    for (int idx = tid; idx < K_ * 32; idx += 256) {
        int k = idx >> 5, c = idx & 31;
        *(float4*)&Vs[k * 128 + c*4] =
            *(const float4*)&V[((size_t)b * K_ + k) * H_ + hc + c*4];
    }
    for (int i = tid; i < T_ * K_; i += 256)
        as[(i / K_) * 51 + (i % K_)] = alpha[(size_t)b * T_ * K_ + i];
    if (tid < T_) bs[tid] = beta[(size_t)b * T_ + tid];
    __syncthreads();

    const int hi = tid & 15, ti = tid >> 4;
    u64 acc[4][4];
    #pragma unroll
    for (int j = 0; j < 4; j++)
        #pragma unroll
        for (int p = 0; p < 4; p++) acc[j][p] = 0ull;

    for (int k = 0; k < K_; k++) {
        F4U2 v0, v1;
        v0.f4 = *(const float4*)&Vs[k * 128 + hi*8];
        v1.f4 = *(const float4*)&Vs[k * 128 + hi*8 + 4];
        #pragma unroll
        for (int j = 0; j < 4; j++) {
            float a = as[(ti + 16*j) * 51 + k];
            u64 a2 = pack2(a, a);
            acc[j][0] = fma2(a2, v0.u[0], acc[j][0]);
            acc[j][1] = fma2(a2, v0.u[1], acc[j][1]);
            acc[j][2] = fma2(a2, v1.u[0], acc[j][2]);
            acc[j][3] = fma2(a2, v1.u[1], acc[j][3]);
        }
    }
    #pragma unroll
    for (int j = 0; j < 4; j++) {
        int t = ti + 16*j;
        float bv  = bs[t];
        float obv = 1.f - bv;
        size_t base = ((size_t)b * T_ + t) * H_ + hc + hi*8;
        float4 s0 = *(const float4*)&s_t[base];
        float4 s1 = *(const float4*)&s_t[base + 4];
        float2 c0 = unpack2(acc[j][0]);
        float2 c1 = unpack2(acc[j][1]);
        float2 c2 = unpack2(acc[j][2]);
        float2 c3 = unpack2(acc[j][3]);
        float4 o0, o1;
        o0.x = fmaf(bv, s0.x, obv * c0.x);
        o0.y = fmaf(bv, s0.y, obv * c0.y);
        o0.z = fmaf(bv, s0.z, obv * c1.x);
        o0.w = fmaf(bv, s0.w, obv * c1.y);
        o1.x = fmaf(bv, s1.x, obv * c2.x);
        o1.y = fmaf(bv, s1.y, obv * c2.y);
        o1.z = fmaf(bv, s1.z, obv * c3.x);
        o1.w = fmaf(bv, s1.w, obv * c3.y);
        *(float4*)&out[base]     = o0;
        *(float4*)&out[base + 4] = o1;
    }
}

extern "C" void kernel_launch(void* const* d_in, const int* in_sizes, int n_in,
                              void* d_out, int out_size)
{
    (void)in_sizes; (void)n_in; (void)out_size;
    const float* V   = (const float*)d_in[0];   // (B,K,H)
    const float* h_t = (const float*)d_in[1];   // (B,T,H)
    const float* s_t = (const float*)d_in[2];   // (B,T,H)
    const float* Wv  = (const float*)d_in[3];   // (K,H)
    const float* Wg  = (const float*)d_in[4];   // (K,H)
    const float* Ws_ = (const float*)d_in[5];   // (K,H)
    const float* Wh  = (const float*)d_in[6];   // (1,K)

    float* out       = (float*)d_out;
    float* out_chat  = out;                 // (B,T,H)
    float* out_alpha = out + BTH;           // (B,T,K)
    float* out_beta  = out + BTH + BTK;     // (B,T,1)

    wperm_kernel<<<192, 128>>>(Wv, Wg, Ws_);
    gemm_mma_kernel<<<708, 128>>>(V, h_t, s_t);
    zsoft_kernel<<<dim3(2, B_), 256>>>(Wh, out_alpha, out_beta);
    chat_kernel<<<dim3(H_ / 128, B_), 256>>>(V, s_t, out_alpha, out_beta, out_chat);
}

// round 6
// speedup vs baseline: 2.3684x; 1.1304x over previous
#include <cuda_runtime.h>
#include <cstdint>

// Problem dims
#define B_  256
#define T_  64
#define K_  49
#define H_  512
#define A_  49
#define BT  (B_ * T_)            // 16384
#define BK  (B_ * K_)            // 12544
#define BTH ((size_t)BT * H_)    // 8388608
#define BTK ((size_t)BT * K_)    // 802816
#define CP  52                   // padded row pitch for scratch [*, 52]

// Scratch (device globals; no allocations allowed)
__device__ __align__(16) float g_cv[B_ * K_ * CP];   // content_v  [b,k,52]
__device__ __align__(16) float g_cg[B_ * T_ * CP];   // content_g  [b,t,52]
__device__ __align__(16) float g_cs[B_ * T_ * CP];   // s_t@Ws^T   [b,t,52]
__device__ __align__(16) float g_Wp[3 * 32768];      // permuted W fragments

typedef unsigned long long u64;

__device__ __forceinline__ float tanh_approx(float x) {
    float y;
    asm("tanh.approx.f32 %0, %1;" : "=f"(y) : "f"(x));
    return y;
}
__device__ __forceinline__ u64 pack2(float lo, float hi) {
    u64 d;
    asm("mov.b64 %0, {%1, %2};" : "=l"(d) : "f"(lo), "f"(hi));
    return d;
}
__device__ __forceinline__ uint32_t s2u(const void* p) {
    uint32_t a;
    asm("{ .reg .u64 t; cvta.to.shared.u64 t, %1; cvt.u32.u64 %0, t; }"
        : "=r"(a) : "l"(p));
    return a;
}
__device__ __forceinline__ void cpa16(uint32_t dst, const void* src) {
    asm volatile("cp.async.cg.shared.global [%0], [%1], 16;"
                 :: "r"(dst), "l"(src) : "memory");
}
__device__ __forceinline__ void mma_tf32(float* d,
                                         float a0, float a1, float a2, float a3,
                                         float b0, float b1) {
    asm volatile(
        "mma.sync.aligned.m16n8k8.row.col.f32.tf32.tf32.f32 "
        "{%0,%1,%2,%3}, {%4,%5,%6,%7}, {%8,%9}, {%0,%1,%2,%3};"
        : "+f"(d[0]), "+f"(d[1]), "+f"(d[2]), "+f"(d[3])
        : "r"(__float_as_uint(a0)), "r"(__float_as_uint(a1)),
          "r"(__float_as_uint(a2)), "r"(__float_as_uint(a3)),
          "r"(__float_as_uint(b0)), "r"(__float_as_uint(b1)));
}

// ---------------------------------------------------------------------------
// Permute W matrices into mma.sync B-fragment order.
// ---------------------------------------------------------------------------
__global__ __launch_bounds__(128)
void wperm_kernel(const float* __restrict__ Wv, const float* __restrict__ Wg,
                  const float* __restrict__ Ws_)
{
    int tid = blockIdx.x * 128 + threadIdx.x;       // 0..24575
    int mat = tid / 8192;
    int rem = tid % 8192;
    int S   = rem / 128;
    int j   = (rem / 32) % 4;
    int l   = rem % 32;
    int g = l >> 2, tg = l & 3;
    int k = S * 8 + tg;
    int r0 = 16 * j + g, r1 = r0 + 8;
    const float* W = (mat == 0) ? Wv : (mat == 1) ? Wg : Ws_;
    float4 F;
    F.x = (r0 < A_) ? W[(size_t)r0 * H_ + k]     : 0.f;
    F.y = (r0 < A_) ? W[(size_t)r0 * H_ + k + 4] : 0.f;
    F.z = (r1 < A_) ? W[(size_t)r1 * H_ + k]     : 0.f;
    F.w = (r1 < A_) ? W[(size_t)r1 * H_ + k + 4] : 0.f;
    *(float4*)&g_Wp[(size_t)mat * 32768 + (size_t)rem * 4] = F;
}

// ---------------------------------------------------------------------------
// tf32 mma.sync content GEMM (unchanged from round 5).
// ---------------------------------------------------------------------------
__global__ __launch_bounds__(128, 3)
void gemm_mma_kernel(const float* __restrict__ V,   const float* __restrict__ h_t,
                     const float* __restrict__ s_t)
{
    __shared__ __align__(16) float  Xs[64][68];
    __shared__ __align__(16) float4 Bs[1024];       // [s][j][lane]

    const float* X; const float* wp; float* out; int row0;
    const int bid = blockIdx.x;
    if (bid < 196)      { X = V;   wp = g_Wp;          out = g_cv; row0 = bid * 64; }
    else if (bid < 452) { X = h_t; wp = g_Wp + 32768;  out = g_cg; row0 = (bid - 196) * 64; }
    else                { X = s_t; wp = g_Wp + 65536;  out = g_cs; row0 = (bid - 452) * 64; }

    const int tid  = threadIdx.x;
    const int wid  = tid >> 5;
    const int lane = tid & 31;
    const int g    = lane >> 2;
    const int tg   = lane & 3;
    const uint32_t xs_u = s2u(&Xs[0][0]);
    const uint32_t bs_u = s2u(&Bs[0]);

    float acc[8][4];
    #pragma unroll
    for (int n = 0; n < 8; n++)
        #pragma unroll
        for (int c = 0; c < 4; c++) acc[n][c] = 0.f;

    for (int c = 0; c < 8; c++) {
        __syncthreads();
        #pragma unroll
        for (int i = 0; i < 8; i++) {
            int idx = tid + i * 128;
            int r = idx >> 4, c4 = idx & 15;
            cpa16(xs_u + (uint32_t)(r * 68 + c4 * 4) * 4,
                  &X[(size_t)(row0 + r) * H_ + c * 64 + c4 * 4]);
        }
        #pragma unroll
        for (int i = 0; i < 8; i++) {
            int idx = tid + i * 128;
            cpa16(bs_u + (uint32_t)idx * 16, wp + (size_t)c * 4096 + (size_t)idx * 4);
        }
        asm volatile("cp.async.commit_group;" ::: "memory");
        asm volatile("cp.async.wait_group 0;" ::: "memory");
        __syncthreads();

        #pragma unroll
        for (int s = 0; s < 8; s++) {
            float a0 = Xs[16*wid + g    ][s*8 + tg    ];
            float a1 = Xs[16*wid + g + 8][s*8 + tg    ];
            float a2 = Xs[16*wid + g    ][s*8 + tg + 4];
            float a3 = Xs[16*wid + g + 8][s*8 + tg + 4];
            #pragma unroll
            for (int j = 0; j < 4; j++) {
                float4 bf = Bs[(s*4 + j) * 32 + lane];
                mma_tf32(acc[2*j],     a0, a1, a2, a3, bf.x, bf.y);
                mma_tf32(acc[2*j + 1], a0, a1, a2, a3, bf.z, bf.w);
            }
        }
    }

    const int r0g = row0 + 16 * wid + g;
    #pragma unroll
    for (int n = 0; n < 8; n++) {
        int col0 = n * 8 + tg * 2;
        if (col0 < CP) {
            *(u64*)&out[(size_t)r0g * CP + col0]       = pack2(acc[n][0], acc[n][1]);
            *(u64*)&out[(size_t)(r0g + 8) * CP + col0] = pack2(acc[n][2], acc[n][3]);
        }
    }
}

// ---------------------------------------------------------------------------
// zsoft: z_t + z_ext + softmax(alpha) + extended softmax(beta). (unchanged)
// ---------------------------------------------------------------------------
#define TZ 32
#define ZP 53

__global__ __launch_bounds__(256)
void zsoft_kernel(const float* __restrict__ Wh,
                  float* __restrict__ out_alpha, float* __restrict__ out_beta)
{
    const int b  = blockIdx.y;
    const int t0 = blockIdx.x * TZ;
    __shared__ float cvs[K_ * ZP];
    __shared__ float cgs[TZ * ZP];
    __shared__ float css[TZ * ZP];
    __shared__ float whs[A_];
    __shared__ float zes[TZ];
    __shared__ float zs[TZ * 50];
    const int tid = threadIdx.x;

    for (int i = tid; i < K_ * A_; i += 256) {
        int k = i / A_, a = i % A_;
        cvs[k * ZP + a] = g_cv[((size_t)b * K_ + k) * CP + a];
    }
    for (int i = tid; i < TZ * A_; i += 256) {
        int t = i / A_, a = i % A_;
        size_t src = ((size_t)b * T_ + t0 + t) * CP + a;
        cgs[t * ZP + a] = g_cg[src];
        css[t * ZP + a] = g_cs[src];
    }
    if (tid < A_) whs[tid] = Wh[tid];
    __syncthreads();

    for (int item = tid; item < TZ * K_ + TZ; item += 256) {
        const float* rowA;
        const float* rowB;
        if (item < TZ * K_) {
            int t = item / K_, k = item % K_;
            rowA = &cgs[t * ZP];
            rowB = &cvs[k * ZP];
        } else {
            int t = item - TZ * K_;
            rowA = &cgs[t * ZP];
            rowB = &css[t * ZP];
        }
        float s0 = 0.f, s1 = 0.f;
        #pragma unroll
        for (int a = 0; a < 48; a += 2) {
            s0 = fmaf(tanh_approx(rowA[a]   + rowB[a]),   whs[a],   s0);
            s1 = fmaf(tanh_approx(rowA[a+1] + rowB[a+1]), whs[a+1], s1);
        }
        s0 = fmaf(tanh_approx(rowA[48] + rowB[48]), whs[48], s0);
        float z = s0 + s1;
        if (item < TZ * K_) {
            int t = item / K_, k = item % K_;
            zs[t * 50 + k] = z;
        } else {
            zes[item - TZ * K_] = z;
        }
    }
    __syncthreads();

    const int warp = tid >> 5, lane = tid & 31;
    for (int t = warp; t < TZ; t += 8) {
        float z1 = (lane < K_)      ? zs[t*50 + lane]      : -1e30f;
        float z2 = (lane + 32 < K_) ? zs[t*50 + lane + 32] : -1e30f;
        float m = fmaxf(z1, z2);
        #pragma unroll
        for (int o = 16; o; o >>= 1) m = fmaxf(m, __shfl_xor_sync(0xffffffffu, m, o));
        float e1 = (lane < K_)      ? __expf(z1 - m) : 0.f;
        float e2 = (lane + 32 < K_) ? __expf(z2 - m) : 0.f;
        float s = e1 + e2;
        #pragma unroll
        for (int o = 16; o; o >>= 1) s += __shfl_xor_sync(0xffffffffu, s, o);
        float inv = 1.f / s;
        size_t bt = (size_t)b * T_ + t0 + t;
        if (lane < K_)      out_alpha[bt * K_ + lane]      = e1 * inv;
        if (lane + 32 < K_) out_alpha[bt * K_ + lane + 32] = e2 * inv;
        if (lane == 0) {
            float ze = zes[t];
            float m2 = fmaxf(m, ze);
            float ee = __expf(ze - m2);
            float denom = s * __expf(m - m2) + ee;
            out_beta[bt] = ee / denom;
        }
    }
}

// ---------------------------------------------------------------------------
// chat via tf32 mma: c_hat = beta*s_t + (1-beta)*(alpha @ V).
// Block (hc 128-wide, b); 256 thr = 8 warps = 4 m16-tiles x 2 n64-halves.
// Warp: m16 x n64 = 8 m16n8k8 tiles, K=49 padded to 56 (7 ksteps).
// Vs pitch 136 (==8 mod 32) -> B-frag scalar LDS pattern is conflict-free.
// ---------------------------------------------------------------------------
#define VP 136
#define AP 57

__global__ __launch_bounds__(256)
void chat_mma_kernel(const float* __restrict__ V, const float* __restrict__ s_t,
                     const float* __restrict__ alpha, const float* __restrict__ beta,
                     float* __restrict__ out)
{
    const int b  = blockIdx.y;
    const int hc = blockIdx.x * 128;
    __shared__ __align__(16) float Vs[56][VP];   // rows 49..55 zero
    __shared__ float as[T_][AP];                 // cols 49..55 zero
    __shared__ float bs[T_];
    const int tid = threadIdx.x;

    // V tile load (rows >= 49 zero-filled)
    for (int idx = tid; idx < 56 * 32; idx += 256) {
        int k = idx >> 5, c = idx & 31;
        float4 v = make_float4(0.f, 0.f, 0.f, 0.f);
        if (k < K_)
            v = *(const float4*)&V[((size_t)b * K_ + k) * H_ + hc + c*4];
        *(float4*)&Vs[k][c*4] = v;
    }
    // alpha tile (cols >= 49 zero)
    for (int i = tid; i < T_ * 56; i += 256) {
        int t = i / 56, k = i % 56;
        as[t][k] = (k < K_) ? alpha[((size_t)b * T_ + t) * K_ + k] : 0.f;
    }
    if (tid < T_) bs[tid] = beta[(size_t)b * T_ + tid];
    __syncthreads();

    const int wid  = tid >> 5;
    const int lane = tid & 31;
    const int g    = lane >> 2;
    const int tg   = lane & 3;
    const int mw   = wid & 3;      // m16 tile (t-range 16mw..16mw+15)
    const int nh   = wid >> 2;     // n 64-half

    float acc[8][4];
    #pragma unroll
    for (int j = 0; j < 8; j++)
        #pragma unroll
        for (int c = 0; c < 4; c++) acc[j][c] = 0.f;

    #pragma unroll
    for (int ks = 0; ks < 7; ks++) {
        float a0 = as[16*mw + g    ][ks*8 + tg    ];
        float a1 = as[16*mw + g + 8][ks*8 + tg    ];
        float a2 = as[16*mw + g    ][ks*8 + tg + 4];
        float a3 = as[16*mw + g + 8][ks*8 + tg + 4];
        #pragma unroll
        for (int j = 0; j < 8; j++) {
            int n = nh*64 + j*8 + g;
            float b0 = Vs[ks*8 + tg    ][n];
            float b1 = Vs[ks*8 + tg + 4][n];
            mma_tf32(acc[j], a0, a1, a2, a3, b0, b1);
        }
    }

    // Blend epilogue: D frag (g,2tg),(g,2tg+1),(g+8,2tg),(g+8,2tg+1)
    const int t0 = 16*mw + g;
    const float bv0 = bs[t0],     ob0 = 1.f - bv0;
    const float bv1 = bs[t0 + 8], ob1 = 1.f - bv1;
    #pragma unroll
    for (int j = 0; j < 8; j++) {
        int col = hc + nh*64 + j*8 + 2*tg;
        size_t base0 = ((size_t)b * T_ + t0)     * H_ + col;
        size_t base1 = ((size_t)b * T_ + t0 + 8) * H_ + col;
        float2 s0 = *(const float2*)&s_t[base0];
        float2 s1 = *(const float2*)&s_t[base1];
        float2 o0, o1;
        o0.x = fmaf(bv0, s0.x, ob0 * acc[j][0]);
        o0.y = fmaf(bv0, s0.y, ob0 * acc[j][1]);
        o1.x = fmaf(bv1, s1.x, ob1 * acc[j][2]);
        o1.y = fmaf(bv1, s1.y, ob1 * acc[j][3]);
        *(float2*)&out[base0] = o0;
        *(float2*)&out[base1] = o1;
    }
}

extern "C" void kernel_launch(void* const* d_in, const int* in_sizes, int n_in,
                              void* d_out, int out_size)
{
    (void)in_sizes; (void)n_in; (void)out_size;
    const float* V   = (const float*)d_in[0];   // (B,K,H)
    const float* h_t = (const float*)d_in[1];   // (B,T,H)
    const float* s_t = (const float*)d_in[2];   // (B,T,H)
    const float* Wv  = (const float*)d_in[3];   // (K,H)
    const float* Wg  = (const float*)d_in[4];   // (K,H)
    const float* Ws_ = (const float*)d_in[5];   // (K,H)
    const float* Wh  = (const float*)d_in[6];   // (1,K)

    float* out       = (float*)d_out;
    float* out_chat  = out;                 // (B,T,H)
    float* out_alpha = out + BTH;           // (B,T,K)
    float* out_beta  = out + BTH + BTK;     // (B,T,1)

    wperm_kernel<<<192, 128>>>(Wv, Wg, Ws_);
    gemm_mma_kernel<<<708, 128>>>(V, h_t, s_t);
    zsoft_kernel<<<dim3(2, B_), 256>>>(Wh, out_alpha, out_beta);
    chat_mma_kernel<<<dim3(4, B_), 256>>>(V, s_t, out_alpha, out_beta, out_chat);
}